// round 1
// baseline (speedup 1.0000x reference)
#include <cuda_runtime.h>
#include <cuda_bf16.h>

// StandardDeviationPooling: 4x4 window, stride 2, VALID.
// Input:  [64, 1024, 1024, 1] fp32   Output: [64, 511*511] fp32
// std = sqrt(max(E[x^2] - E[x]^2, 0)) per window (matches reference exactly).
//
// Each thread: 2 output cols x 8 output rows.
//  - 2 output cols (2c, 2c+1) consume input cols 4c..4c+7 -> two aligned float4 loads/row.
//  - vertical reuse: rolling 2-row "pair sums"; each input row loaded once per strip.

#define H_IN 1024
#define W_IN 1024
#define H_OUT 511
#define W_OUT 511
#define ROWS_PER_THREAD 8

__global__ __launch_bounds__(256, 4)
void std_pool_kernel(const float* __restrict__ in, float* __restrict__ out) {
    const int c  = blockIdx.x * blockDim.x + threadIdx.x;   // col-pair index 0..255
    if (c >= 256) return;
    const int r0 = blockIdx.y * ROWS_PER_THREAD;            // first output row of strip
    const int b  = blockIdx.z;

    const float* __restrict__ inb  = in  + (size_t)b * H_IN * W_IN;
    float* __restrict__       outb = out + (size_t)b * H_OUT * W_OUT;

    const int  ic   = 4 * c;                 // first input col
    const bool has2 = (ic + 7) < W_IN;       // second float4 in-bounds (c < 255)
    const int  oc0  = 2 * c;

    // previous pair (rows 2j, 2j+1) sums: s=sum, q=sum of squares; per output col 0/1
    float ps0 = 0.f, ps1 = 0.f, pq0 = 0.f, pq1 = 0.f;

    #pragma unroll
    for (int j = 0; j <= ROWS_PER_THREAD; ++j) {
        const int irow = 2 * (r0 + j);
        float cs0 = 0.f, cs1 = 0.f, cq0 = 0.f, cq1 = 0.f;

        if (irow + 1 < H_IN) {
            #pragma unroll
            for (int rr = 0; rr < 2; ++rr) {
                const float* rowp = inb + (size_t)(irow + rr) * W_IN + ic;
                const float4 a = *reinterpret_cast<const float4*>(rowp);
                float4 d;
                if (has2) d = *reinterpret_cast<const float4*>(rowp + 4);
                else      d = make_float4(0.f, 0.f, 0.f, 0.f);

                cs0 += a.x + a.y + a.z + a.w;
                cq0 = fmaf(a.x, a.x, fmaf(a.y, a.y, fmaf(a.z, a.z, fmaf(a.w, a.w, cq0))));
                cs1 += a.z + a.w + d.x + d.y;
                cq1 = fmaf(a.z, a.z, fmaf(a.w, a.w, fmaf(d.x, d.x, fmaf(d.y, d.y, cq1))));
            }
        }

        if (j > 0) {
            const int orow = r0 + j - 1;
            if (orow < H_OUT) {
                const float inv_n = 1.0f / 16.0f;
                {
                    const float s = ps0 + cs0, q = pq0 + cq0;
                    const float m = s * inv_n;
                    const float v = fmaxf(fmaf(-m, m, q * inv_n), 0.f);
                    outb[(size_t)orow * W_OUT + oc0] = sqrtf(v);
                }
                if (oc0 + 1 < W_OUT) {
                    const float s = ps1 + cs1, q = pq1 + cq1;
                    const float m = s * inv_n;
                    const float v = fmaxf(fmaf(-m, m, q * inv_n), 0.f);
                    outb[(size_t)orow * W_OUT + oc0 + 1] = sqrtf(v);
                }
            }
        }
        ps0 = cs0; ps1 = cs1; pq0 = cq0; pq1 = cq1;
    }
}

extern "C" void kernel_launch(void* const* d_in, const int* in_sizes, int n_in,
                              void* d_out, int out_size) {
    const float* in = (const float*)d_in[0];
    float* out = (float*)d_out;
    (void)in_sizes; (void)n_in; (void)out_size;

    // 256 col-pair threads cover 511 output cols; 64 row-strips of 8 cover 511 rows; 64 batches.
    dim3 block(256, 1, 1);
    dim3 grid(1, (H_OUT + ROWS_PER_THREAD - 1) / ROWS_PER_THREAD, 64);
    std_pool_kernel<<<grid, block>>>(in, out);
}